// round 3
// baseline (speedup 1.0000x reference)
#include <cuda_runtime.h>
#include <math.h>

#define NN 131072
#define FN 64
#define FF 16
#define HH 128
#define EE 2097152
#define BB 256
#define LL 32
#define G4 512

// ---------------- scratch (device globals; no allocation) ----------------
__device__ int   g_deg[NN];
__device__ int   g_off[NN];
__device__ int   g_cur[NN];
__device__ int   g_bsum[128];
__device__ int   g_csr[EE];
__device__ float g_mean[NN*HH];     // layer1 uses stride 64, layer2 stride 128
__device__ float g_h1[NN*HH];
__device__ float g_emb[NN*HH];
__device__ float g_gsum[BB*HH];
__device__ int   g_bcnt[BB];
__device__ float g_Xg[BB*LL*G4];
__device__ float g_hst[BB*HH];
__device__ float g_cst[BB*HH];
__device__ float g_G[BB*G4];

// ---------------- init ----------------
__global__ void k_zero(){
  int i = blockIdx.x*256 + threadIdx.x;
  if (i < NN) g_deg[i] = 0;
  if (i < BB) g_bcnt[i] = 0;
  if (i < BB*HH){ g_gsum[i]=0.f; g_hst[i]=0.f; g_cst[i]=0.f; }
}

// ---------------- CSR build ----------------
__global__ void k_degree(const int* __restrict__ ei){
  int e = blockIdx.x*256+threadIdx.x;
  if (e < EE) atomicAdd(&g_deg[ei[EE+e]], 1);
}

__global__ void k_scanA(){
  __shared__ int s[256];
  int tid=threadIdx.x;
  int base = blockIdx.x*1024 + tid*4;
  int t = g_deg[base]+g_deg[base+1]+g_deg[base+2]+g_deg[base+3];
  s[tid]=t; __syncthreads();
  for(int o=128;o>0;o>>=1){ if(tid<o) s[tid]+=s[tid+o]; __syncthreads(); }
  if(tid==0) g_bsum[blockIdx.x]=s[0];
}

__global__ void k_scanB(){
  __shared__ int s[128];
  int t=threadIdx.x;
  int v=g_bsum[t]; s[t]=v; __syncthreads();
  for(int o=1;o<128;o<<=1){
    int a = (t>=o)? s[t-o] : 0; __syncthreads();
    s[t]+=a; __syncthreads();
  }
  g_bsum[t]=s[t]-v;   // exclusive block base
}

__global__ void k_scanC(){
  __shared__ int s[256];
  int tid=threadIdx.x;
  int base = blockIdx.x*1024 + tid*4;
  int d0=g_deg[base],d1=g_deg[base+1],d2=g_deg[base+2],d3=g_deg[base+3];
  int tot=d0+d1+d2+d3;
  s[tid]=tot; __syncthreads();
  for(int o=1;o<256;o<<=1){
    int a=(tid>=o)? s[tid-o]:0; __syncthreads();
    s[tid]+=a; __syncthreads();
  }
  int run = g_bsum[blockIdx.x] + s[tid]-tot;
  g_off[base  ]=run; g_cur[base  ]=run; run+=d0;
  g_off[base+1]=run; g_cur[base+1]=run; run+=d1;
  g_off[base+2]=run; g_cur[base+2]=run; run+=d2;
  g_off[base+3]=run; g_cur[base+3]=run;
}

__global__ void k_csr(const int* __restrict__ ei){
  int e = blockIdx.x*256+threadIdx.x;
  if (e < EE){
    int src = ei[e], dst = ei[EE+e];
    int p = atomicAdd(&g_cur[dst],1);
    g_csr[p]=src;
  }
}

// ---------------- neighbor-mean gathers (warp per node) ----------------
__global__ void k_agg1(const float* __restrict__ x){
  int w = (blockIdx.x*256+threadIdx.x)>>5;
  int lane = threadIdx.x&31;
  if (w>=NN) return;
  int beg=g_off[w], d=g_deg[w];
  float ax=0.f, ay=0.f;
  for(int i=0;i<d;i++){
    int src=g_csr[beg+i];
    float2 v = *(const float2*)(x + (size_t)src*FN + lane*2);
    ax+=v.x; ay+=v.y;
  }
  float inv = 1.0f/(float)max(d,1);
  float2 o; o.x=ax*inv; o.y=ay*inv;
  *(float2*)(g_mean + (size_t)w*FN + lane*2) = o;
}

__global__ void k_agg2(){
  int w = (blockIdx.x*256+threadIdx.x)>>5;
  int lane=threadIdx.x&31;
  if (w>=NN) return;
  int beg=g_off[w], d=g_deg[w];
  float4 acc = {0.f,0.f,0.f,0.f};
  for(int i=0;i<d;i++){
    int src=g_csr[beg+i];
    float4 v=*(const float4*)(g_h1 + (size_t)src*HH + lane*4);
    acc.x+=v.x; acc.y+=v.y; acc.z+=v.z; acc.w+=v.w;
  }
  float inv=1.f/(float)max(d,1);
  acc.x*=inv; acc.y*=inv; acc.z*=inv; acc.w*=inv;
  *(float4*)(g_mean + (size_t)w*HH + lane*4) = acc;
}

// ---------------- tiled SGEMM: C = act([A1|A2] @ [W1|W2]^T + bias1 + bias2) ----------------
// BM=128, BN=64, BK=16, 256 threads, 8x4 microtile. Row/col counts assumed divisible.
template<bool RELU, bool GATHER>
__global__ void __launch_bounds__(256) k_gemm(
    const float* __restrict__ A1, int K1,
    const float* __restrict__ A2, int K2,
    const float* __restrict__ W1, const float* __restrict__ W2,
    const float* __restrict__ bias1, const float* __restrict__ bias2,
    const int* __restrict__ gidx,
    float* __restrict__ C, int OUT)
{
  __shared__ __align__(16) float As[128][20];
  __shared__ __align__(16) float Ws[16][72];
  int tid=threadIdx.x;
  int m0=blockIdx.x*128;
  int j0=blockIdx.y*64;
  int ty=tid>>4, tx=tid&15;
  float acc[8][4];
  #pragma unroll
  for(int i=0;i<8;i++){
    #pragma unroll
    for(int j=0;j<4;j++) acc[i][j]=0.f;
  }
  int K=K1+K2;
  for(int k0=0;k0<K;k0+=16){
    #pragma unroll
    for(int p=0;p<2;p++){
      int u=tid+p*256;
      int mm=u>>2, kq=(u&3)*4;
      int m=m0+mm;
      int r = GATHER ? gidx[m] : m;
      int k=k0+kq;
      float4 v;
      if(k<K1) v = *(const float4*)(A1 + (size_t)r*K1 + k);
      else     v = *(const float4*)(A2 + (size_t)r*K2 + (k-K1));
      *(float4*)&As[mm][kq] = v;
    }
    {
      int kc=tid&3, jj=tid>>2;
      int j=j0+jj, k=k0+kc*4;
      float4 w;
      if(k<K1) w = *(const float4*)(W1 + (size_t)j*K1 + k);
      else     w = *(const float4*)(W2 + (size_t)j*K2 + (k-K1));
      Ws[kc*4+0][jj]=w.x; Ws[kc*4+1][jj]=w.y; Ws[kc*4+2][jj]=w.z; Ws[kc*4+3][jj]=w.w;
    }
    __syncthreads();
    #pragma unroll
    for(int kk=0;kk<16;kk++){
      float4 b4 = *(const float4*)&Ws[kk][tx*4];
      #pragma unroll
      for(int i=0;i<8;i++){
        float a=As[ty*8+i][kk];
        acc[i][0] += a*b4.x;
        acc[i][1] += a*b4.y;
        acc[i][2] += a*b4.z;
        acc[i][3] += a*b4.w;
      }
    }
    __syncthreads();
  }
  int j=j0+tx*4;
  float c0=0.f,c1=0.f,c2=0.f,c3=0.f;
  if(bias1){ c0=bias1[j]; c1=bias1[j+1]; c2=bias1[j+2]; c3=bias1[j+3]; }
  if(bias2){ c0+=bias2[j]; c1+=bias2[j+1]; c2+=bias2[j+2]; c3+=bias2[j+3]; }
  #pragma unroll
  for(int i=0;i<8;i++){
    int m=m0+ty*8+i;
    float4 o;
    o.x=acc[i][0]+c0; o.y=acc[i][1]+c1; o.z=acc[i][2]+c2; o.w=acc[i][3]+c3;
    if(RELU){ o.x=fmaxf(o.x,0.f); o.y=fmaxf(o.y,0.f); o.z=fmaxf(o.z,0.f); o.w=fmaxf(o.w,0.f); }
    *(float4*)(C + (size_t)m*OUT + j) = o;
  }
}

// ---------------- graph mean-pool (batch is sorted) ----------------
__global__ void k_gsum(const int* __restrict__ batch){
  int f=threadIdx.x;       // 128
  int n0=blockIdx.x*128;
  int cur=batch[n0];
  float acc=0.f; int rl=0;
  for(int i=0;i<128;i++){
    int n=n0+i;
    int bb=batch[n];
    if(bb!=cur){
      atomicAdd(&g_gsum[cur*HH+f], acc);
      if(f==0) atomicAdd(&g_bcnt[cur], rl);
      acc=0.f; rl=0; cur=bb;
    }
    acc += g_emb[(size_t)n*HH+f];
    rl++;
  }
  atomicAdd(&g_gsum[cur*HH+f], acc);
  if(f==0) atomicAdd(&g_bcnt[cur], rl);
}

// ---------------- LSTM recurrent step: G = Xg[:,t,:] + h @ Whh^T ----------------
__global__ void __launch_bounds__(256) k_lstm_gate(const float* __restrict__ Whh, int t){
  __shared__ __align__(16) float hs[16][128];
  __shared__ __align__(16) float wsT[128][68];
  int tid=threadIdx.x;
  int r0=blockIdx.x*16, j0=blockIdx.y*64;
  #pragma unroll
  for(int p=0;p<2;p++){
    int u=tid+p*256;               // 512 float4 = 16x128 floats
    int kc=u&31, rr=u>>5;
    *(float4*)&hs[rr][kc*4] = *(const float4*)(g_hst + (r0+rr)*HH + kc*4);
  }
  #pragma unroll
  for(int p=0;p<8;p++){
    int u=tid+p*256;               // 2048 float4 = 64x128 floats
    int kc=u&31, jj=u>>5;
    float4 w = *(const float4*)(Whh + (size_t)(j0+jj)*HH + kc*4);
    wsT[kc*4+0][jj]=w.x; wsT[kc*4+1][jj]=w.y; wsT[kc*4+2][jj]=w.z; wsT[kc*4+3][jj]=w.w;
  }
  __syncthreads();
  int ty=tid>>4, tx=tid&15;
  float a0=0.f,a1=0.f,a2=0.f,a3=0.f;
  #pragma unroll 4
  for(int k=0;k<128;k++){
    float a=hs[ty][k];
    float4 b=*(const float4*)&wsT[k][tx*4];
    a0+=a*b.x; a1+=a*b.y; a2+=a*b.z; a3+=a*b.w;
  }
  int b_=r0+ty, j=j0+tx*4;
  const float* xg = g_Xg + ((size_t)b_*LL + t)*G4 + j;
  float4 o; o.x=a0+xg[0]; o.y=a1+xg[1]; o.z=a2+xg[2]; o.w=a3+xg[3];
  *(float4*)(g_G + b_*G4 + j) = o;
}

__device__ __forceinline__ float sigf(float v){ return 1.f/(1.f+expf(-v)); }

__global__ void k_lstm_cell(const int* __restrict__ path_len, int t){
  int idx = blockIdx.x*256+threadIdx.x;  // BB*HH
  int b = idx>>7;
  int k = idx&127;
  const float* Gr = g_G + b*G4;
  float ig=Gr[k], fg=Gr[128+k], gg=Gr[256+k], og=Gr[384+k];
  float c = g_cst[idx];
  float cn = sigf(fg)*c + sigf(ig)*tanhf(gg);
  float hn = sigf(og)*tanhf(cn);
  if (t < path_len[b]){ g_cst[idx]=cn; g_hst[idx]=hn; }
}

// ---------------- final: flow MLP + concat + scoring MLP ----------------
__global__ void k_combine(const float* __restrict__ flow, const float* __restrict__ Wf,
   const float* __restrict__ bf, const float* __restrict__ Ws1, const float* __restrict__ bs1,
   const float* __restrict__ Ws2, const float* __restrict__ bs2, float* __restrict__ out)
{
  __shared__ __align__(16) float comb[320];
  __shared__ float red[128];
  int b=blockIdx.x, tid=threadIdx.x;   // 128 threads
  float cnt=(float)max(g_bcnt[b],1);
  comb[tid]      = g_gsum[b*HH+tid]/cnt;
  comb[128+tid]  = g_hst[b*HH+tid];
  if(tid<64){
    float a=bf[tid];
    #pragma unroll
    for(int i=0;i<16;i++) a += flow[b*FF+i]*Wf[tid*FF+i];
    comb[256+tid]=fmaxf(a,0.f);
  }
  __syncthreads();
  float s=bs1[tid];
  const float4* w4=(const float4*)(Ws1 + (size_t)tid*320);
  const float4* c4=(const float4*)comb;
  #pragma unroll 8
  for(int k=0;k<80;k++){
    float4 w=w4[k], c=c4[k];
    s += w.x*c.x + w.y*c.y + w.z*c.z + w.w*c.w;
  }
  s=fmaxf(s,0.f);
  red[tid]=s*Ws2[tid];
  __syncthreads();
  for(int o=64;o>0;o>>=1){ if(tid<o) red[tid]+=red[tid+o]; __syncthreads(); }
  if(tid==0) out[b]=red[0]+bs2[0];
}

// ---------------- launch ----------------
extern "C" void kernel_launch(void* const* d_in, const int* in_sizes, int n_in,
                              void* d_out, int out_size){
  const float* x   =(const float*)d_in[0];
  const int*   ei  =(const int*)  d_in[1];
  const int*   batch=(const int*) d_in[2];
  const int*   pidx=(const int*)  d_in[3];
  const int*   plen=(const int*)  d_in[4];
  const float* flow=(const float*)d_in[5];
  const float* Wl1=(const float*)d_in[6];
  const float* Wr1=(const float*)d_in[7];
  const float* b1 =(const float*)d_in[8];
  const float* Wl2=(const float*)d_in[9];
  const float* Wr2=(const float*)d_in[10];
  const float* b2 =(const float*)d_in[11];
  const float* Wih=(const float*)d_in[12];
  const float* Whh=(const float*)d_in[13];
  const float* bih=(const float*)d_in[14];
  const float* bhh=(const float*)d_in[15];
  const float* Wf =(const float*)d_in[16];
  const float* bf =(const float*)d_in[17];
  const float* Ws1=(const float*)d_in[18];
  const float* bs1=(const float*)d_in[19];
  const float* Ws2=(const float*)d_in[20];
  const float* bs2=(const float*)d_in[21];
  float* out=(float*)d_out;

  float *p_mean,*p_h1,*p_emb,*p_xg;
  cudaGetSymbolAddress((void**)&p_mean, g_mean);
  cudaGetSymbolAddress((void**)&p_h1,   g_h1);
  cudaGetSymbolAddress((void**)&p_emb,  g_emb);
  cudaGetSymbolAddress((void**)&p_xg,   g_Xg);

  k_zero<<<NN/256,256>>>();
  k_degree<<<EE/256,256>>>(ei);
  k_scanA<<<128,256>>>();
  k_scanB<<<1,128>>>();
  k_scanC<<<128,256>>>();
  k_csr<<<EE/256,256>>>(ei);

  // SAGE layer 1
  k_agg1<<<NN/8,256>>>(x);
  k_gemm<true,false><<<dim3(NN/128,2),256>>>(p_mean,FN, x,FN, Wl1,Wr1, b1,nullptr, nullptr, p_h1, HH);

  // SAGE layer 2
  k_agg2<<<NN/8,256>>>();
  k_gemm<true,false><<<dim3(NN/128,2),256>>>(p_mean,HH, p_h1,HH, Wl2,Wr2, b2,nullptr, nullptr, p_emb, HH);

  // graph pooling
  k_gsum<<<NN/128,128>>>(batch);

  // LSTM input precompute: Xg[b,t,:] = node_emb[path_idx] @ Wih^T + bih + bhh
  k_gemm<false,true><<<dim3(BB*LL/128,8),256>>>(p_emb,HH, nullptr,0, Wih,nullptr, bih,bhh, pidx, p_xg, G4);

  // LSTM recurrence
  for(int t=0;t<LL;t++){
    k_lstm_gate<<<dim3(BB/16,8),256>>>(Whh, t);
    k_lstm_cell<<<BB*HH/256,256>>>(plen, t);
  }

  // final scoring
  k_combine<<<BB,128>>>(flow,Wf,bf,Ws1,bs1,Ws2,bs2,out);
}